// round 12
// baseline (speedup 1.0000x reference)
#include <cuda_runtime.h>
#include <cuda_fp16.h>
#include <stdint.h>

#define HID 128
#define NN 100000
#define EE 600000

// ---------------- scratch (static device globals; no allocs) ----------------
__device__ __half g_h16  [(size_t)NN * HID];  // layer-0 features (fp16)
__device__ __half g_h116 [(size_t)NN * HID];  // layer-1 output (fp16, relu'd)
__device__ __half g_mean16[(size_t)NN * HID]; // fp16 mean (GEMM A)
__device__ __half g_W16 [2 * HID * 2 * HID];  // [layer][j(128)][k(256: Wl|Wr)] fp16
__device__ int    g_cnt [NN];
__device__ int    g_rowstart[NN];
__device__ int    g_cursor  [NN];
__device__ int    g_csr [EE];
__device__ int    g_bsum[256];

// ---------------- CSR build ----------------
__global__ void k_zero_cnt(int n) {
    int i = blockIdx.x * blockDim.x + threadIdx.x;
    if (i < n) g_cnt[i] = 0;
}

__global__ void k_hist(const int* __restrict__ dst, int e) {
    int i = blockIdx.x * blockDim.x + threadIdx.x;
    if (i < e) atomicAdd(&g_cnt[dst[i]], 1);
}

__global__ void k_scanA(int n) {
    __shared__ int s[1024];
    int i = blockIdx.x * 1024 + threadIdx.x;
    int v = (i < n) ? g_cnt[i] : 0;
    s[threadIdx.x] = v;
    __syncthreads();
    #pragma unroll
    for (int off = 1; off < 1024; off <<= 1) {
        int t = (threadIdx.x >= off) ? s[threadIdx.x - off] : 0;
        __syncthreads();
        s[threadIdx.x] += t;
        __syncthreads();
    }
    if (i < n) g_rowstart[i] = s[threadIdx.x] - v;   // exclusive within block
    if (threadIdx.x == 1023) g_bsum[blockIdx.x] = s[1023];
}

// scanC folds the cross-block prefix (block reduction of g_bsum).
__global__ void k_scanC(int n) {
    __shared__ int red[1024];
    int t = threadIdx.x;
    red[t] = (t < blockIdx.x) ? g_bsum[t] : 0;   // nb <= 98 < 1024
    __syncthreads();
    #pragma unroll
    for (int off = 512; off > 0; off >>= 1) {
        if (t < off) red[t] += red[t + off];
        __syncthreads();
    }
    int base = red[0];
    int i = blockIdx.x * 1024 + t;
    if (i < n) {
        int rs = g_rowstart[i] + base;
        g_rowstart[i] = rs;
        g_cursor[i]   = rs;
    }
}

__global__ void k_fill(const int* __restrict__ src, const int* __restrict__ dst, int e) {
    int i = blockIdx.x * blockDim.x + threadIdx.x;
    if (i < e) {
        int p = atomicAdd(&g_cursor[dst[i]], 1);
        g_csr[p] = src[i];
    }
}

// ---------------- feature gather: h16 = fp16(emb[x]) ----------------
__global__ void k_gather(const int* __restrict__ x, const float4* __restrict__ emb, int n) {
    int i = blockIdx.x * blockDim.x + threadIdx.x;
    int total = n * (HID / 4);
    if (i < total) {
        int node = i >> 5;
        int c    = i & 31;
        float4 v = emb[(size_t)x[node] * 32 + c];
        __half2 p0 = __floats2half2_rn(v.x, v.y);
        __half2 p1 = __floats2half2_rn(v.z, v.w);
        ((uint2*)g_h16)[i] = make_uint2(*(uint32_t*)&p0, *(uint32_t*)&p1);
    }
}

// ---------------- weight pack: concat [Wl;Wr] -> fp16, B[j][k(256)] ----------------
__global__ void k_pack(const float* __restrict__ Wl1, const float* __restrict__ Wr1,
                       const float* __restrict__ Wl2, const float* __restrict__ Wr2) {
    int idx = blockIdx.x * blockDim.x + threadIdx.x;   // 2*128*256 = 65536
    if (idx >= 2 * HID * 2 * HID) return;
    int layer = idx >> 15;
    int j = (idx >> 8) & 127;
    int k = idx & 255;
    const float* Wl = layer ? Wl2 : Wl1;
    const float* Wr = layer ? Wr2 : Wr1;
    float w = (k < 128) ? Wl[j * 128 + k] : Wr[j * 128 + (k - 128)];
    g_W16[idx] = __float2half_rn(w);
}

// ---------------- mean aggregation (one warp per node, fp16 in / fp16 out) ---------
__global__ void k_agg(int layer, int n) {
    int gw   = (blockIdx.x * blockDim.x + threadIdx.x) >> 5;
    int lane = threadIdx.x & 31;
    if (gw >= n) return;
    const uint2* h2 = (const uint2*)(layer ? g_h116 : g_h16);   // row = 32 uint2
    int deg = g_cnt[gw];
    int st  = g_rowstart[gw];
    float4 acc = make_float4(0.f, 0.f, 0.f, 0.f);
    for (int e = 0; e < deg; e++) {
        int s = g_csr[st + e];
        uint2 v = h2[(size_t)s * 32 + lane];
        float2 f0 = __half22float2(*(__half2*)&v.x);
        float2 f1 = __half22float2(*(__half2*)&v.y);
        acc.x += f0.x; acc.y += f0.y; acc.z += f1.x; acc.w += f1.y;
    }
    float sc = 1.0f / (float)max(deg, 1);
    __half2 p0 = __floats2half2_rn(acc.x * sc, acc.y * sc);
    __half2 p1 = __floats2half2_rn(acc.z * sc, acc.w * sc);
    ((uint2*)g_mean16)[(size_t)gw * 32 + lane] = make_uint2(*(uint32_t*)&p0, *(uint32_t*)&p1);
}

// ---------------- tensor-core GEMM: out = relu([mean|h] @ W^T + bias) ----------------
__device__ __forceinline__ void mma16816h(float* d, const uint32_t* a, const uint32_t* b) {
    asm volatile(
        "mma.sync.aligned.m16n8k16.row.col.f32.f16.f16.f32 "
        "{%0,%1,%2,%3}, {%4,%5,%6,%7}, {%8,%9}, {%0,%1,%2,%3};\n"
        : "+f"(d[0]), "+f"(d[1]), "+f"(d[2]), "+f"(d[3])
        : "r"(a[0]), "r"(a[1]), "r"(a[2]), "r"(a[3]), "r"(b[0]), "r"(b[1]));
}

// CTA: 128 rows x 128 cols; 512 threads / 16 warps.
// Warp w: row stripe (w>>1)*16, column half (w&1)*64 -> warp = 16 rows x 64 cols.
// acc = 32 regs/thread -> ~2x warps/SM vs the 256-thread variant.
// A pre-converted fp16 (one LDG.64 per row-half per ks, prefetched, MLP=2).
// Full B (j 128 x k 256) staged once in 64KB smem, 16B-granule XOR swizzle.
// k-permutation: lane (c=l%4) covers mma-k {2c,2c+1,2c+8,2c+9} = mem-k {4c..4c+3}.
__global__ __launch_bounds__(512, 2) void k_gemm(int layer, const float* __restrict__ bias,
                                                 float* __restrict__ out32, int n) {
    __shared__ __half sB[128 * 256];   // 64KB

    const __half* Am16 = g_mean16;
    const __half* Ah16 = layer ? g_h116 : g_h16;
    const __half* W = g_W16 + (size_t)layer * 32768;

    int tid = threadIdx.x;
    int w = tid >> 5, l = tid & 31;
    int c = l & 3, g = l >> 2;
    int colbase = (w & 1) * 64;
    int r0 = blockIdx.x * 128 + (w >> 1) * 16;
    int rg  = min(r0 + g,     n - 1);
    int rg8 = min(r0 + g + 8, n - 1);

    // stage all of B: 4096 granules of 16B, swizzled
    {
        const uint4* Wg = (const uint4*)W;
        uint4* S = (uint4*)sB;
        #pragma unroll
        for (int f = tid; f < 4096; f += 512) {
            int j  = f >> 5;
            int gi = f & 31;
            S[j * 32 + (gi ^ (j & 15))] = Wg[f];
        }
    }

    float acc[8][4];
    #pragma unroll
    for (int nt = 0; nt < 8; nt++) {
        float b0 = __ldg(bias + colbase + nt * 8 + 2 * c);
        float b1 = __ldg(bias + colbase + nt * 8 + 2 * c + 1);
        acc[nt][0] = b0; acc[nt][1] = b1; acc[nt][2] = b0; acc[nt][3] = b1;
    }
    __syncthreads();

    const __half* am0 = Am16 + (size_t)rg  * HID + 4 * c;
    const __half* am1 = Am16 + (size_t)rg8 * HID + 4 * c;
    const __half* ah0 = Ah16 + (size_t)rg  * HID + 4 * c;
    const __half* ah1 = Ah16 + (size_t)rg8 * HID + 4 * c;

    uint2 va = *(const uint2*)am0;     // ks=0 (mean, mem-k 4c..4c+3)
    uint2 vb = *(const uint2*)am1;

    #pragma unroll
    for (int ks = 0; ks < 16; ks++) {
        uint2 nva, nvb;
        if (ks < 15) {                 // prefetch next ks
            int kn = ks + 1;
            const __half* p0 = (kn < 8) ? am0 + kn * 16 : ah0 + (kn - 8) * 16;
            const __half* p1 = (kn < 8) ? am1 + kn * 16 : ah1 + (kn - 8) * 16;
            nva = *(const uint2*)p0;
            nvb = *(const uint2*)p1;
        }

        uint32_t a[4] = { va.x, vb.x, va.y, vb.y };
        #pragma unroll
        for (int nt = 0; nt < 8; nt++) {
            int j = colbase + nt * 8 + g;
            uint32_t off = (uint32_t)j * 512
                         + (uint32_t)(((2 * ks + (c >> 1)) ^ (j & 15)) << 4)
                         + (uint32_t)((c & 1) << 3);
            uint2 bv = *(const uint2*)((const char*)sB + off);
            mma16816h(acc[nt], a, (const uint32_t*)&bv);
        }
        va = nva; vb = nvb;
    }

    int row0 = r0 + g, row1 = r0 + g + 8;
    if (layer == 0) {
        #pragma unroll
        for (int nt = 0; nt < 8; nt++) {
            int col = colbase + nt * 8 + 2 * c;
            if (row0 < n) {
                __half2 p = __floats2half2_rn(fmaxf(acc[nt][0], 0.f), fmaxf(acc[nt][1], 0.f));
                *(uint32_t*)(g_h116 + (size_t)row0 * HID + col) = *(uint32_t*)&p;
            }
            if (row1 < n) {
                __half2 p = __floats2half2_rn(fmaxf(acc[nt][2], 0.f), fmaxf(acc[nt][3], 0.f));
                *(uint32_t*)(g_h116 + (size_t)row1 * HID + col) = *(uint32_t*)&p;
            }
        }
    } else {
        #pragma unroll
        for (int nt = 0; nt < 8; nt++) {
            int col = colbase + nt * 8 + 2 * c;
            if (row0 < n) {
                float2 o = make_float2(fmaxf(acc[nt][0], 0.f), fmaxf(acc[nt][1], 0.f));
                *(float2*)(out32 + (size_t)row0 * HID + col) = o;
            }
            if (row1 < n) {
                float2 o = make_float2(fmaxf(acc[nt][2], 0.f), fmaxf(acc[nt][3], 0.f));
                *(float2*)(out32 + (size_t)row1 * HID + col) = o;
            }
        }
    }
}

// ---------------- launch (R9 serial order; single stream) ----------------
extern "C" void kernel_launch(void* const* d_in, const int* in_sizes, int n_in,
                              void* d_out, int out_size) {
    const int*   x    = (const int*)  d_in[0];
    const int*   ei   = (const int*)  d_in[1];
    const float* emb  = (const float*)d_in[2];
    const float* Wl1  = (const float*)d_in[3];
    const float* bl1  = (const float*)d_in[4];
    const float* Wr1  = (const float*)d_in[5];
    const float* Wl2  = (const float*)d_in[6];
    const float* bl2  = (const float*)d_in[7];
    const float* Wr2  = (const float*)d_in[8];

    int n = in_sizes[0];
    int e = in_sizes[1] / 2;
    const int* src = ei;
    const int* dst = ei + e;

    int nb = (n + 1023) / 1024;

    // setup
    k_gather<<<(n * 32 + 255) / 256, 256>>>(x, (const float4*)emb, n);
    k_pack  <<<(2 * HID * 2 * HID + 255) / 256, 256>>>(Wl1, Wr1, Wl2, Wr2);
    k_zero_cnt<<<(n + 255) / 256, 256>>>(n);

    // CSR build
    k_hist <<<(e + 255) / 256, 256>>>(dst, e);
    k_scanA<<<nb, 1024>>>(n);
    k_scanC<<<nb, 1024>>>(n);
    k_fill <<<(e + 255) / 256, 256>>>(src, dst, e);

    // layer 1
    k_agg <<<(n + 7) / 8,    256>>>(0, n);
    k_gemm<<<(n + 127) / 128, 512>>>(0, bl1, (float*)d_out, n);  // writes g_h116

    // layer 2
    k_agg <<<(n + 7) / 8,    256>>>(1, n);
    k_gemm<<<(n + 127) / 128, 512>>>(1, bl2, (float*)d_out, n);  // writes d_out
}

// round 13
// speedup vs baseline: 1.0933x; 1.0933x over previous
#include <cuda_runtime.h>
#include <cuda_fp16.h>
#include <stdint.h>

#define HID 128
#define NN 100000
#define EE 600000

// ---------------- scratch (static device globals; no allocs) ----------------
__device__ __half g_h16  [(size_t)NN * HID];  // layer-0 features (fp16)
__device__ __half g_h116 [(size_t)NN * HID];  // layer-1 output (fp16, relu'd)
__device__ __half g_mean16[(size_t)NN * HID]; // fp16 mean (GEMM A)
__device__ __half g_W16 [2 * HID * 2 * HID];  // [layer][j(128)][k(256: Wl|Wr)] fp16
__device__ int    g_cnt [NN];
__device__ int    g_rowstart[NN];
__device__ int    g_cursor  [NN];
__device__ int    g_csr [EE];
__device__ int    g_bsum[256];

// ---------------- CSR build ----------------
__global__ void k_zero_cnt(int n) {
    int i = blockIdx.x * blockDim.x + threadIdx.x;
    if (i < n) g_cnt[i] = 0;
}

__global__ void k_hist(const int* __restrict__ dst, int e) {
    int i = blockIdx.x * blockDim.x + threadIdx.x;
    if (i < e) atomicAdd(&g_cnt[dst[i]], 1);
}

__global__ void k_scanA(int n) {
    __shared__ int s[1024];
    int i = blockIdx.x * 1024 + threadIdx.x;
    int v = (i < n) ? g_cnt[i] : 0;
    s[threadIdx.x] = v;
    __syncthreads();
    #pragma unroll
    for (int off = 1; off < 1024; off <<= 1) {
        int t = (threadIdx.x >= off) ? s[threadIdx.x - off] : 0;
        __syncthreads();
        s[threadIdx.x] += t;
        __syncthreads();
    }
    if (i < n) g_rowstart[i] = s[threadIdx.x] - v;   // exclusive within block
    if (threadIdx.x == 1023) g_bsum[blockIdx.x] = s[1023];
}

// scanC folds the cross-block prefix (block reduction of g_bsum).
__global__ void k_scanC(int n) {
    __shared__ int red[1024];
    int t = threadIdx.x;
    red[t] = (t < blockIdx.x) ? g_bsum[t] : 0;   // nb <= 98 < 1024
    __syncthreads();
    #pragma unroll
    for (int off = 512; off > 0; off >>= 1) {
        if (t < off) red[t] += red[t + off];
        __syncthreads();
    }
    int base = red[0];
    int i = blockIdx.x * 1024 + t;
    if (i < n) {
        int rs = g_rowstart[i] + base;
        g_rowstart[i] = rs;
        g_cursor[i]   = rs;
    }
}

__global__ void k_fill(const int* __restrict__ src, const int* __restrict__ dst, int e) {
    int i = blockIdx.x * blockDim.x + threadIdx.x;
    if (i < e) {
        int p = atomicAdd(&g_cursor[dst[i]], 1);
        g_csr[p] = src[i];
    }
}

// ---------------- feature gather: h16 = fp16(emb[x]) ----------------
__global__ void k_gather(const int* __restrict__ x, const float4* __restrict__ emb, int n) {
    int i = blockIdx.x * blockDim.x + threadIdx.x;
    int total = n * (HID / 4);
    if (i < total) {
        int node = i >> 5;
        int c    = i & 31;
        float4 v = emb[(size_t)x[node] * 32 + c];
        __half2 p0 = __floats2half2_rn(v.x, v.y);
        __half2 p1 = __floats2half2_rn(v.z, v.w);
        ((uint2*)g_h16)[i] = make_uint2(*(uint32_t*)&p0, *(uint32_t*)&p1);
    }
}

// ---------------- weight pack: concat [Wl;Wr] -> fp16, B[j][k(256)] ----------------
__global__ void k_pack(const float* __restrict__ Wl1, const float* __restrict__ Wr1,
                       const float* __restrict__ Wl2, const float* __restrict__ Wr2) {
    int idx = blockIdx.x * blockDim.x + threadIdx.x;   // 2*128*256 = 65536
    if (idx >= 2 * HID * 2 * HID) return;
    int layer = idx >> 15;
    int j = (idx >> 8) & 127;
    int k = idx & 255;
    const float* Wl = layer ? Wl2 : Wl1;
    const float* Wr = layer ? Wr2 : Wr1;
    float w = (k < 128) ? Wl[j * 128 + k] : Wr[j * 128 + (k - 128)];
    g_W16[idx] = __float2half_rn(w);
}

// ---------------- mean aggregation (one warp per node, fp16 in / fp16 out) ---------
// Edge loop manually unrolled x4 -> 4 independent gathers in flight (MLP=4).
__global__ void k_agg(int layer, int n) {
    int gw   = (blockIdx.x * blockDim.x + threadIdx.x) >> 5;
    int lane = threadIdx.x & 31;
    if (gw >= n) return;
    const uint2* h2 = (const uint2*)(layer ? g_h116 : g_h16);   // row = 32 uint2
    int deg = g_cnt[gw];
    int st  = g_rowstart[gw];
    float4 acc = make_float4(0.f, 0.f, 0.f, 0.f);

    int e = 0;
    for (; e + 4 <= deg; e += 4) {
        int s0 = g_csr[st + e + 0];
        int s1 = g_csr[st + e + 1];
        int s2 = g_csr[st + e + 2];
        int s3 = g_csr[st + e + 3];
        uint2 v0 = h2[(size_t)s0 * 32 + lane];
        uint2 v1 = h2[(size_t)s1 * 32 + lane];
        uint2 v2 = h2[(size_t)s2 * 32 + lane];
        uint2 v3 = h2[(size_t)s3 * 32 + lane];
        float2 a0 = __half22float2(*(__half2*)&v0.x), b0 = __half22float2(*(__half2*)&v0.y);
        float2 a1 = __half22float2(*(__half2*)&v1.x), b1 = __half22float2(*(__half2*)&v1.y);
        float2 a2 = __half22float2(*(__half2*)&v2.x), b2 = __half22float2(*(__half2*)&v2.y);
        float2 a3 = __half22float2(*(__half2*)&v3.x), b3 = __half22float2(*(__half2*)&v3.y);
        acc.x += (a0.x + a1.x) + (a2.x + a3.x);
        acc.y += (a0.y + a1.y) + (a2.y + a3.y);
        acc.z += (b0.x + b1.x) + (b2.x + b3.x);
        acc.w += (b0.y + b1.y) + (b2.y + b3.y);
    }
    for (; e < deg; e++) {
        int s = g_csr[st + e];
        uint2 v = h2[(size_t)s * 32 + lane];
        float2 f0 = __half22float2(*(__half2*)&v.x);
        float2 f1 = __half22float2(*(__half2*)&v.y);
        acc.x += f0.x; acc.y += f0.y; acc.z += f1.x; acc.w += f1.y;
    }

    float sc = 1.0f / (float)max(deg, 1);
    __half2 p0 = __floats2half2_rn(acc.x * sc, acc.y * sc);
    __half2 p1 = __floats2half2_rn(acc.z * sc, acc.w * sc);
    ((uint2*)g_mean16)[(size_t)gw * 32 + lane] = make_uint2(*(uint32_t*)&p0, *(uint32_t*)&p1);
}

// ---------------- tensor-core GEMM: out = relu([mean|h] @ W^T + bias) ----------------
__device__ __forceinline__ void mma16816h(float* d, const uint32_t* a, const uint32_t* b) {
    asm volatile(
        "mma.sync.aligned.m16n8k16.row.col.f32.f16.f16.f32 "
        "{%0,%1,%2,%3}, {%4,%5,%6,%7}, {%8,%9}, {%0,%1,%2,%3};\n"
        : "+f"(d[0]), "+f"(d[1]), "+f"(d[2]), "+f"(d[3])
        : "r"(a[0]), "r"(a[1]), "r"(a[2]), "r"(a[3]), "r"(b[0]), "r"(b[1]));
}

// CTA: 128 rows x 128 cols; 256 threads / 8 warps, warp = 16 rows x 128 cols.
// (R9-proven layout.) A pre-converted fp16 (one LDG.64 per row-half per ks,
// prefetched, MLP=2). Full B (j 128 x k 256) staged once in 64KB smem,
// 16B-granule XOR swizzle. k-permutation: lane (c=l%4) covers mma-k
// {2c,2c+1,2c+8,2c+9} = mem-k {4c..4c+3}.
__global__ __launch_bounds__(256, 2) void k_gemm(int layer, const float* __restrict__ bias,
                                                 float* __restrict__ out32, int n) {
    __shared__ __half sB[128 * 256];   // 64KB

    const __half* Am16 = g_mean16;
    const __half* Ah16 = layer ? g_h116 : g_h16;
    const __half* W = g_W16 + (size_t)layer * 32768;

    int tid = threadIdx.x;
    int w = tid >> 5, l = tid & 31;
    int c = l & 3, g = l >> 2;
    int r0 = blockIdx.x * 128 + w * 16;
    int rg  = min(r0 + g,     n - 1);
    int rg8 = min(r0 + g + 8, n - 1);

    // stage all of B: 4096 granules of 16B, swizzled
    {
        const uint4* Wg = (const uint4*)W;
        uint4* S = (uint4*)sB;
        #pragma unroll
        for (int f = tid; f < 4096; f += 256) {
            int j  = f >> 5;
            int gi = f & 31;
            S[j * 32 + (gi ^ (j & 15))] = Wg[f];
        }
    }

    float acc[16][4];
    #pragma unroll
    for (int nt = 0; nt < 16; nt++) {
        float b0 = __ldg(bias + nt * 8 + 2 * c);
        float b1 = __ldg(bias + nt * 8 + 2 * c + 1);
        acc[nt][0] = b0; acc[nt][1] = b1; acc[nt][2] = b0; acc[nt][3] = b1;
    }
    __syncthreads();

    const __half* am0 = Am16 + (size_t)rg  * HID + 4 * c;
    const __half* am1 = Am16 + (size_t)rg8 * HID + 4 * c;
    const __half* ah0 = Ah16 + (size_t)rg  * HID + 4 * c;
    const __half* ah1 = Ah16 + (size_t)rg8 * HID + 4 * c;

    uint2 va = *(const uint2*)am0;     // ks=0 (mean, mem-k 4c..4c+3)
    uint2 vb = *(const uint2*)am1;

    #pragma unroll
    for (int ks = 0; ks < 16; ks++) {
        uint2 nva, nvb;
        if (ks < 15) {                 // prefetch next ks
            int kn = ks + 1;
            const __half* p0 = (kn < 8) ? am0 + kn * 16 : ah0 + (kn - 8) * 16;
            const __half* p1 = (kn < 8) ? am1 + kn * 16 : ah1 + (kn - 8) * 16;
            nva = *(const uint2*)p0;
            nvb = *(const uint2*)p1;
        }

        uint32_t a[4] = { va.x, vb.x, va.y, vb.y };
        #pragma unroll
        for (int nt = 0; nt < 16; nt++) {
            int j = nt * 8 + g;
            uint32_t off = (uint32_t)j * 512
                         + (uint32_t)(((2 * ks + (c >> 1)) ^ (j & 15)) << 4)
                         + (uint32_t)((c & 1) << 3);
            uint2 bv = *(const uint2*)((const char*)sB + off);
            mma16816h(acc[nt], a, (const uint32_t*)&bv);
        }
        va = nva; vb = nvb;
    }

    int row0 = r0 + g, row1 = r0 + g + 8;
    if (layer == 0) {
        #pragma unroll
        for (int nt = 0; nt < 16; nt++) {
            int col = nt * 8 + 2 * c;
            if (row0 < n) {
                __half2 p = __floats2half2_rn(fmaxf(acc[nt][0], 0.f), fmaxf(acc[nt][1], 0.f));
                *(uint32_t*)(g_h116 + (size_t)row0 * HID + col) = *(uint32_t*)&p;
            }
            if (row1 < n) {
                __half2 p = __floats2half2_rn(fmaxf(acc[nt][2], 0.f), fmaxf(acc[nt][3], 0.f));
                *(uint32_t*)(g_h116 + (size_t)row1 * HID + col) = *(uint32_t*)&p;
            }
        }
    } else {
        #pragma unroll
        for (int nt = 0; nt < 16; nt++) {
            int col = nt * 8 + 2 * c;
            if (row0 < n) {
                float2 o = make_float2(fmaxf(acc[nt][0], 0.f), fmaxf(acc[nt][1], 0.f));
                *(float2*)(out32 + (size_t)row0 * HID + col) = o;
            }
            if (row1 < n) {
                float2 o = make_float2(fmaxf(acc[nt][2], 0.f), fmaxf(acc[nt][3], 0.f));
                *(float2*)(out32 + (size_t)row1 * HID + col) = o;
            }
        }
    }
}

// ---------------- launch (fork CSR onto side stream; R11-proven capture) ----------
extern "C" void kernel_launch(void* const* d_in, const int* in_sizes, int n_in,
                              void* d_out, int out_size) {
    const int*   x    = (const int*)  d_in[0];
    const int*   ei   = (const int*)  d_in[1];
    const float* emb  = (const float*)d_in[2];
    const float* Wl1  = (const float*)d_in[3];
    const float* bl1  = (const float*)d_in[4];
    const float* Wr1  = (const float*)d_in[5];
    const float* Wl2  = (const float*)d_in[6];
    const float* bl2  = (const float*)d_in[7];
    const float* Wr2  = (const float*)d_in[8];

    int n = in_sizes[0];
    int e = in_sizes[1] / 2;
    const int* src = ei;
    const int* dst = ei + e;

    int nb = (n + 1023) / 1024;

    cudaStream_t side;
    cudaEvent_t evFork, evJoin;
    cudaStreamCreateWithFlags(&side, cudaStreamNonBlocking);
    cudaEventCreateWithFlags(&evFork, cudaEventDisableTiming);
    cudaEventCreateWithFlags(&evJoin, cudaEventDisableTiming);

    cudaEventRecord(evFork, 0);
    cudaStreamWaitEvent(side, evFork, 0);

    // side: CSR build (data-independent of gather/pack)
    k_zero_cnt<<<(n + 255) / 256, 256, 0, side>>>(n);
    k_hist    <<<(e + 255) / 256, 256, 0, side>>>(dst, e);
    k_scanA   <<<nb, 1024, 0, side>>>(n);
    k_scanC   <<<nb, 1024, 0, side>>>(n);
    k_fill    <<<(e + 255) / 256, 256, 0, side>>>(src, dst, e);
    cudaEventRecord(evJoin, side);

    // main: gather + pack (overlapped with CSR)
    k_gather<<<(n * 32 + 255) / 256, 256>>>(x, (const float4*)emb, n);
    k_pack  <<<(2 * HID * 2 * HID + 255) / 256, 256>>>(Wl1, Wr1, Wl2, Wr2);

    cudaStreamWaitEvent(0, evJoin, 0);

    // layer 1
    k_agg <<<(n + 7) / 8,    256>>>(0, n);
    k_gemm<<<(n + 127) / 128, 256>>>(0, bl1, (float*)d_out, n);  // writes g_h116

    // layer 2
    k_agg <<<(n + 7) / 8,    256>>>(1, n);
    k_gemm<<<(n + 127) / 128, 256>>>(1, bl2, (float*)d_out, n);  // writes d_out
}